// round 2
// baseline (speedup 1.0000x reference)
#include <cuda_runtime.h>
#include <cuda_bf16.h>
#include <cstdio>

#define D 128
#define ESZ 20
#define MAX_NODES 20000
#define MAX_EDGES 600000
#define CUTOFF 5.0f

// ---------------- scratch (static device bss; no allocations) ----------------
__device__ __align__(16) float g_h1 [MAX_NODES * D];        // silu(ns@Wm1+b)
__device__ __align__(16) float g_so [MAX_NODES * 3 * D];    // scalar_output
__device__ __align__(16) float g_s  [MAX_NODES * D];        // s accumulator
__device__ __align__(16) float g_v  [MAX_NODES * 3 * D];    // v accumulator [n][c][d]
__device__ __align__(16) float g_Uv [MAX_NODES * 3 * D];
__device__ __align__(16) float g_Vv [MAX_NODES * 3 * D];
__device__ __align__(16) float g_cat[MAX_NODES * 2 * D];    // [s, Vv_sq]
__device__ __align__(16) float g_ip [MAX_NODES * D];
__device__ __align__(16) float g_h2 [MAX_NODES * D];
__device__ __align__(16) float g_a  [MAX_NODES * 3 * D];

// ---------------- helpers ----------------
__device__ __forceinline__ void red_add_v4(float* addr, float4 v) {
    asm volatile("red.global.add.v4.f32 [%0], {%1, %2, %3, %4};"
                 :: "l"(addr), "f"(v.x), "f"(v.y), "f"(v.z), "f"(v.w) : "memory");
}
__device__ __forceinline__ float silu_f(float x) {
    return x / (1.0f + __expf(-x));
}

// ---------------- init: copy node states into accumulators ----------------
__global__ void init_copy_kernel(const float* __restrict__ ns, const float* __restrict__ nv, int n) {
    int tid = blockIdx.x * blockDim.x + threadIdx.x;
    int stride = gridDim.x * blockDim.x;
    const float4* ns4 = (const float4*)ns;
    const float4* nv4 = (const float4*)nv;
    float4* s4 = (float4*)g_s;
    float4* v4 = (float4*)g_v;
    int cs = n * (D / 4);
    int cv = n * (3 * D / 4);
    for (int i = tid; i < cs; i += stride) s4[i] = ns4[i];
    for (int i = tid; i < cv; i += stride) v4[i] = nv4[i];
}

// ---------------- generic tiled SGEMM: C = act(A[MxK] @ B[KxN] + bias) ----------------
// BM=128, BN=64, BK=16, TM=8, TN=4, 256 threads. K % 16 == 0, N % 64 == 0 required.
template<bool SILU, bool HASBIAS>
__global__ __launch_bounds__(256) void sgemm_kernel(
    const float* __restrict__ A, const float* __restrict__ B,
    const float* __restrict__ bias, float* __restrict__ C,
    int M, int N, int K)
{
    const int BM = 128, BN = 64, BK = 16, TM = 8, TN = 4;
    __shared__ __align__(16) float As[BK][BM + 4];
    __shared__ __align__(16) float Bs[BK][BN];
    int t = threadIdx.x;
    int tx = t & 15;        // 16 col-threads
    int ty = t >> 4;        // 16 row-threads
    int m0 = blockIdx.x * BM;
    int n0 = blockIdx.y * BN;

    float acc[TM][TN];
    #pragma unroll
    for (int i = 0; i < TM; i++)
        #pragma unroll
        for (int j = 0; j < TN; j++) acc[i][j] = 0.0f;

    for (int k0 = 0; k0 < K; k0 += BK) {
        // A tile: 128x16 = 512 float4, 2 per thread, stored transposed
        #pragma unroll
        for (int it = 0; it < 2; it++) {
            int l = t + 256 * it;
            int row = l >> 2;
            int kc = (l & 3) * 4;
            float4 v = make_float4(0.f, 0.f, 0.f, 0.f);
            int gr = m0 + row;
            if (gr < M) v = *(const float4*)&A[(size_t)gr * K + k0 + kc];
            As[kc + 0][row] = v.x;
            As[kc + 1][row] = v.y;
            As[kc + 2][row] = v.z;
            As[kc + 3][row] = v.w;
        }
        // B tile: 16x64 = 256 float4, 1 per thread
        {
            int row = t >> 4;
            int nc = (t & 15) * 4;
            float4 v = *(const float4*)&B[(size_t)(k0 + row) * N + n0 + nc];
            *(float4*)&Bs[row][nc] = v;
        }
        __syncthreads();
        #pragma unroll
        for (int k = 0; k < BK; k++) {
            float4 a0 = *(float4*)&As[k][ty * TM];
            float4 a1 = *(float4*)&As[k][ty * TM + 4];
            float4 b0 = *(float4*)&Bs[k][tx * TN];
            float ar[TM] = {a0.x, a0.y, a0.z, a0.w, a1.x, a1.y, a1.z, a1.w};
            float br[TN] = {b0.x, b0.y, b0.z, b0.w};
            #pragma unroll
            for (int i = 0; i < TM; i++)
                #pragma unroll
                for (int j = 0; j < TN; j++)
                    acc[i][j] += ar[i] * br[j];
        }
        __syncthreads();
    }

    float4 bv = make_float4(0.f, 0.f, 0.f, 0.f);
    if (HASBIAS) bv = *(const float4*)&bias[n0 + tx * TN];
    #pragma unroll
    for (int i = 0; i < TM; i++) {
        int gr = m0 + ty * TM + i;
        if (gr >= M) continue;
        float4 o;
        o.x = acc[i][0] + bv.x;
        o.y = acc[i][1] + bv.y;
        o.z = acc[i][2] + bv.z;
        o.w = acc[i][3] + bv.w;
        if (SILU) { o.x = silu_f(o.x); o.y = silu_f(o.y); o.z = silu_f(o.z); o.w = silu_f(o.w); }
        *(float4*)&C[(size_t)gr * N + n0 + tx * TN] = o;
    }
}

// ---------------- fused edge kernel ----------------
// filter_weight = (edge_states @ Wf + bf) * fc, fused with gather/scatter.
// CTA = 128 threads; threads 0..95 each own 4 consecutive cols of 384 (Wf in regs).
// EB edges per batch; phase1 computes filter_output into smem, phase2 forms
// messages and does v4 global reductions into g_s / g_v.
#define EB 8
__global__ __launch_bounds__(128) void edge_kernel(
    const float* __restrict__ es_g, const float* __restrict__ ev_g,
    const float* __restrict__ norms, const int* __restrict__ eidx,
    const float* __restrict__ Wf, const float* __restrict__ bf,
    const float* __restrict__ nsv, int E)
{
    __shared__ float es_sh[EB][ESZ];
    __shared__ __align__(16) float fo_sh[EB][3 * D];
    __shared__ int   src_sh[EB], dst_sh[EB];
    __shared__ float ev_sh[EB][3];
    __shared__ float fc_sh[EB];

    int t = threadIdx.x;
    bool filt = (t < 96);

    // Wf columns in registers: 20 x 4
    float wf_r[ESZ][4];
    float4 bf4 = make_float4(0.f, 0.f, 0.f, 0.f);
    if (filt) {
        #pragma unroll
        for (int k = 0; k < ESZ; k++) {
            float4 w = *(const float4*)&Wf[k * 384 + 4 * t];
            wf_r[k][0] = w.x; wf_r[k][1] = w.y; wf_r[k][2] = w.z; wf_r[k][3] = w.w;
        }
        bf4 = *(const float4*)&bf[4 * t];
    }

    int nbatch = (E + EB - 1) / EB;
    for (int b = blockIdx.x; b < nbatch; b += gridDim.x) {
        int e0 = b * EB;
        // ---- phase 0: load edge data ----
        for (int l = t; l < EB * ESZ; l += 128) {
            int ge = e0 + l / ESZ;
            es_sh[l / ESZ][l % ESZ] = (ge < E) ? es_g[(size_t)e0 * ESZ + l] : 0.0f;
        }
        if (t < EB) {
            int ge = e0 + t;
            if (ge < E) {
                src_sh[t] = eidx[2 * ge];
                dst_sh[t] = eidx[2 * ge + 1];
                ev_sh[t][0] = ev_g[3 * ge];
                ev_sh[t][1] = ev_g[3 * ge + 1];
                ev_sh[t][2] = ev_g[3 * ge + 2];
                float nrm = norms[ge];
                fc_sh[t] = (nrm < CUTOFF) ? 0.5f * (cospif(nrm / CUTOFF) + 1.0f) : 0.0f;
            } else {
                src_sh[t] = 0; dst_sh[t] = 0;
                ev_sh[t][0] = ev_sh[t][1] = ev_sh[t][2] = 0.f;
                fc_sh[t] = 0.f;
            }
        }
        __syncthreads();

        // ---- phase 1: filter_output = (es@Wf + bf)*fc * scalar_out[src] ----
        if (filt) {
            #pragma unroll 2
            for (int e = 0; e < EB; e++) {
                if (e0 + e >= E) break;
                float4 acc = bf4;
                #pragma unroll
                for (int k = 0; k < ESZ; k++) {
                    float ek = es_sh[e][k];
                    acc.x += ek * wf_r[k][0];
                    acc.y += ek * wf_r[k][1];
                    acc.z += ek * wf_r[k][2];
                    acc.w += ek * wf_r[k][3];
                }
                float fc = fc_sh[e];
                int src = src_sh[e];
                float4 so = *(const float4*)&g_so[(size_t)src * 384 + 4 * t];
                float4 fo;
                fo.x = acc.x * fc * so.x;
                fo.y = acc.y * fc * so.y;
                fo.z = acc.z * fc * so.z;
                fo.w = acc.w * fc * so.w;
                *(float4*)&fo_sh[e][4 * t] = fo;
            }
        }
        __syncthreads();

        // ---- phase 2: messages + scatter ----
        // slot s = t%32 covers 4 channels; group t/32 covers edges {g, g+4}
        {
            int s = t & 31;
            int grp = t >> 5;
            #pragma unroll
            for (int ee = 0; ee < EB / 4; ee++) {
                int e = grp + 4 * ee;
                if (e0 + e >= E) continue;
                int dst = dst_sh[e];
                int src = src_sh[e];
                float4 gn = *(float4*)&fo_sh[e][4 * s];
                float4 ge = *(float4*)&fo_sh[e][D + 4 * s];
                float4 ms = *(float4*)&fo_sh[e][2 * D + 4 * s];
                red_add_v4(&g_s[(size_t)dst * D + 4 * s], ms);
                #pragma unroll
                for (int c = 0; c < 3; c++) {
                    float evc = ev_sh[e][c];
                    float4 nv = *(const float4*)&nsv[((size_t)src * 3 + c) * D + 4 * s];
                    float4 mv;
                    mv.x = nv.x * gn.x + ge.x * evc;
                    mv.y = nv.y * gn.y + ge.y * evc;
                    mv.z = nv.z * gn.z + ge.z * evc;
                    mv.w = nv.w * gn.w + ge.w * evc;
                    red_add_v4(&g_v[((size_t)dst * 3 + c) * D + 4 * s], mv);
                }
            }
        }
        __syncthreads();
    }
}

// ---------------- per-node: Vv_sq, ip, concat ----------------
__global__ void vsq_ip_cat_kernel(int n) {
    int node = blockIdx.x;
    int i = threadIdx.x;  // 128
    float vsq = 0.f, ipv = 0.f;
    #pragma unroll
    for (int c = 0; c < 3; c++) {
        float u = g_Uv[((size_t)node * 3 + c) * D + i];
        float w = g_Vv[((size_t)node * 3 + c) * D + i];
        vsq += w * w;
        ipv += u * w;
    }
    g_cat[(size_t)node * 256 + i]       = g_s[(size_t)node * D + i];
    g_cat[(size_t)node * 256 + D + i]   = vsq;
    g_ip[(size_t)node * D + i]          = ipv;
}

// ---------------- final elementwise ----------------
__global__ void final_kernel(float* __restrict__ out, int n) {
    int node = blockIdx.x;
    int i = threadIdx.x;  // 128
    const float* a = &g_a[(size_t)node * 384];
    float a_ss = a[i];
    float a_sv = a[D + i];
    float a_vv = a[2 * D + i];
    out[(size_t)node * D + i] =
        g_s[(size_t)node * D + i] + a_ss + a_sv * g_ip[(size_t)node * D + i];
    float* vout = out + (size_t)n * D;
    #pragma unroll
    for (int c = 0; c < 3; c++) {
        size_t idx = ((size_t)node * 3 + c) * D + i;
        vout[idx] = g_v[idx] + a_vv * g_Uv[idx];
    }
}

// ---------------- launch ----------------
extern "C" void kernel_launch(void* const* d_in, const int* in_sizes, int n_in,
                              void* d_out, int out_size) {
    const float* ns  = (const float*)d_in[0];
    const float* nv  = (const float*)d_in[1];
    const float* es  = (const float*)d_in[2];
    const float* ev  = (const float*)d_in[3];
    const float* en  = (const float*)d_in[4];
    const int*   ei  = (const int*)  d_in[5];
    const float* Wf  = (const float*)d_in[6];
    const float* bf  = (const float*)d_in[7];
    const float* Wm1 = (const float*)d_in[8];
    const float* bm1 = (const float*)d_in[9];
    const float* Wm2 = (const float*)d_in[10];
    const float* bm2 = (const float*)d_in[11];
    const float* WU  = (const float*)d_in[12];
    const float* WV  = (const float*)d_in[13];
    const float* Wa1 = (const float*)d_in[14];
    const float* ba1 = (const float*)d_in[15];
    const float* Wa2 = (const float*)d_in[16];
    const float* ba2 = (const float*)d_in[17];

    int n = in_sizes[0] / D;          // nodes
    int E = in_sizes[4];              // edges (edge_norms count)
    float* out = (float*)d_out;

    float *p_h1, *p_so, *p_v, *p_Uv, *p_Vv, *p_cat, *p_h2, *p_a;
    cudaGetSymbolAddress((void**)&p_h1,  g_h1);
    cudaGetSymbolAddress((void**)&p_so,  g_so);
    cudaGetSymbolAddress((void**)&p_v,   g_v);
    cudaGetSymbolAddress((void**)&p_Uv,  g_Uv);
    cudaGetSymbolAddress((void**)&p_Vv,  g_Vv);
    cudaGetSymbolAddress((void**)&p_cat, g_cat);
    cudaGetSymbolAddress((void**)&p_h2,  g_h2);
    cudaGetSymbolAddress((void**)&p_a,   g_a);

    // 1. init accumulators s = ns, v = nv
    init_copy_kernel<<<2048, 256>>>(ns, nv, n);

    // 2. H1 = silu(ns @ Wm1 + bm1)   [n,128]
    {
        dim3 grid((n + 127) / 128, 128 / 64);
        sgemm_kernel<true, true><<<grid, 256>>>(ns, Wm1, bm1, p_h1, n, 128, 128);
    }
    // 3. SO = H1 @ Wm2 + bm2         [n,384]
    {
        dim3 grid((n + 127) / 128, 384 / 64);
        sgemm_kernel<false, true><<<grid, 256>>>(p_h1, Wm2, bm2, p_so, n, 384, 128);
    }
    // 4. fused edge kernel
    edge_kernel<<<4096, 128>>>(es, ev, en, ei, Wf, bf, nv, E);

    // 5/6. Uv = v @ WU, Vv = v @ WV  (rows = 3n)
    {
        dim3 grid((3 * n + 127) / 128, 128 / 64);
        sgemm_kernel<false, false><<<grid, 256>>>(p_v, WU, nullptr, p_Uv, 3 * n, 128, 128);
        sgemm_kernel<false, false><<<grid, 256>>>(p_v, WV, nullptr, p_Vv, 3 * n, 128, 128);
    }
    // 7. Vv_sq, ip, cat
    vsq_ip_cat_kernel<<<n, 128>>>(n);

    // 8. H2 = silu(cat @ Wa1 + ba1)  [n,128], K=256
    {
        dim3 grid((n + 127) / 128, 128 / 64);
        sgemm_kernel<true, true><<<grid, 256>>>(p_cat, Wa1, ba1, p_h2, n, 128, 256);
    }
    // 9. A = H2 @ Wa2 + ba2          [n,384]
    {
        dim3 grid((n + 127) / 128, 384 / 64);
        sgemm_kernel<false, true><<<grid, 256>>>(p_h2, Wa2, ba2, p_a, n, 384, 128);
    }
    // 10. final
    final_kernel<<<n, 128>>>(out, n);
}

// round 3
// speedup vs baseline: 1.1848x; 1.1848x over previous
#include <cuda_runtime.h>
#include <cuda_bf16.h>
#include <cstdio>

#define D 128
#define ESZ 20
#define MAX_NODES 20000
#define MAX_EDGES 600000
#define CUTOFF 5.0f

// ---------------- scratch (static device bss; no allocations) ----------------
__device__ __align__(16) float g_h1 [MAX_NODES * D];        // silu(ns@Wm1+b)
__device__ __align__(16) float g_so [MAX_NODES * 3 * D];    // scalar_output
__device__ __align__(16) float g_s  [MAX_NODES * D];        // s accumulator
__device__ __align__(16) float g_v  [MAX_NODES * 3 * D];    // v accumulator [n][c][d]
__device__ __align__(16) float g_Uv [MAX_NODES * 3 * D];
__device__ __align__(16) float g_Vv [MAX_NODES * 3 * D];
__device__ __align__(16) float g_cat[MAX_NODES * 2 * D];    // [s, Vv_sq]
__device__ __align__(16) float g_ip [MAX_NODES * D];
__device__ __align__(16) float g_h2 [MAX_NODES * D];
__device__ __align__(16) float g_a  [MAX_NODES * 3 * D];

// ---------------- helpers ----------------
__device__ __forceinline__ void red_add_v4(float* addr, float4 v) {
    asm volatile("red.global.add.v4.f32 [%0], {%1, %2, %3, %4};"
                 :: "l"(addr), "f"(v.x), "f"(v.y), "f"(v.z), "f"(v.w) : "memory");
}
__device__ __forceinline__ float silu_f(float x) {
    return x / (1.0f + __expf(-x));
}

// ---------------- init: copy node states into accumulators ----------------
__global__ void init_copy_kernel(const float* __restrict__ ns, const float* __restrict__ nv, int n) {
    int tid = blockIdx.x * blockDim.x + threadIdx.x;
    int stride = gridDim.x * blockDim.x;
    const float4* ns4 = (const float4*)ns;
    const float4* nv4 = (const float4*)nv;
    float4* s4 = (float4*)g_s;
    float4* v4 = (float4*)g_v;
    int cs = n * (D / 4);
    int cv = n * (3 * D / 4);
    for (int i = tid; i < cs; i += stride) s4[i] = ns4[i];
    for (int i = tid; i < cv; i += stride) v4[i] = nv4[i];
}

// ---------------- generic tiled SGEMM: C = act(A[MxK] @ B[KxN] + bias) ----------------
// BM=128, BN=64, BK=16, TM=8, TN=4, 256 threads. K % 16 == 0, N % 64 == 0 required.
template<bool SILU, bool HASBIAS>
__global__ __launch_bounds__(256) void sgemm_kernel(
    const float* __restrict__ A, const float* __restrict__ B,
    const float* __restrict__ bias, float* __restrict__ C,
    int M, int N, int K)
{
    const int BM = 128, BN = 64, BK = 16, TM = 8, TN = 4;
    __shared__ __align__(16) float As[BK][BM + 4];
    __shared__ __align__(16) float Bs[BK][BN];
    int t = threadIdx.x;
    int tx = t & 15;
    int ty = t >> 4;
    int m0 = blockIdx.x * BM;
    int n0 = blockIdx.y * BN;

    float acc[TM][TN];
    #pragma unroll
    for (int i = 0; i < TM; i++)
        #pragma unroll
        for (int j = 0; j < TN; j++) acc[i][j] = 0.0f;

    for (int k0 = 0; k0 < K; k0 += BK) {
        #pragma unroll
        for (int it = 0; it < 2; it++) {
            int l = t + 256 * it;
            int row = l >> 2;
            int kc = (l & 3) * 4;
            float4 v = make_float4(0.f, 0.f, 0.f, 0.f);
            int gr = m0 + row;
            if (gr < M) v = *(const float4*)&A[(size_t)gr * K + k0 + kc];
            As[kc + 0][row] = v.x;
            As[kc + 1][row] = v.y;
            As[kc + 2][row] = v.z;
            As[kc + 3][row] = v.w;
        }
        {
            int row = t >> 4;
            int nc = (t & 15) * 4;
            float4 v = *(const float4*)&B[(size_t)(k0 + row) * N + n0 + nc];
            *(float4*)&Bs[row][nc] = v;
        }
        __syncthreads();
        #pragma unroll
        for (int k = 0; k < BK; k++) {
            float4 a0 = *(float4*)&As[k][ty * TM];
            float4 a1 = *(float4*)&As[k][ty * TM + 4];
            float4 b0 = *(float4*)&Bs[k][tx * TN];
            float ar[TM] = {a0.x, a0.y, a0.z, a0.w, a1.x, a1.y, a1.z, a1.w};
            float br[TN] = {b0.x, b0.y, b0.z, b0.w};
            #pragma unroll
            for (int i = 0; i < TM; i++)
                #pragma unroll
                for (int j = 0; j < TN; j++)
                    acc[i][j] += ar[i] * br[j];
        }
        __syncthreads();
    }

    float4 bv = make_float4(0.f, 0.f, 0.f, 0.f);
    if (HASBIAS) bv = *(const float4*)&bias[n0 + tx * TN];
    #pragma unroll
    for (int i = 0; i < TM; i++) {
        int gr = m0 + ty * TM + i;
        if (gr >= M) continue;
        float4 o;
        o.x = acc[i][0] + bv.x;
        o.y = acc[i][1] + bv.y;
        o.z = acc[i][2] + bv.z;
        o.w = acc[i][3] + bv.w;
        if (SILU) { o.x = silu_f(o.x); o.y = silu_f(o.y); o.z = silu_f(o.z); o.w = silu_f(o.w); }
        *(float4*)&C[(size_t)gr * N + n0 + tx * TN] = o;
    }
}

// ---------------- dual SGEMM: C1 = A@B1, C2 = A@B2 (shared A pass) ----------------
// BM=128, BN=64 (full N=128 in two blocks? N=128 here, BN=64), BK=16, 256 thr.
__global__ __launch_bounds__(256) void sgemm_dual_kernel(
    const float* __restrict__ A,
    const float* __restrict__ B1, const float* __restrict__ B2,
    float* __restrict__ C1, float* __restrict__ C2,
    int M, int N, int K)
{
    const int BM = 128, BN = 64, BK = 16, TM = 8, TN = 4;
    __shared__ __align__(16) float As[BK][BM + 4];
    __shared__ __align__(16) float Bs1[BK][BN];
    __shared__ __align__(16) float Bs2[BK][BN];
    int t = threadIdx.x;
    int tx = t & 15;
    int ty = t >> 4;
    int m0 = blockIdx.x * BM;
    int n0 = blockIdx.y * BN;

    float acc1[TM][TN], acc2[TM][TN];
    #pragma unroll
    for (int i = 0; i < TM; i++)
        #pragma unroll
        for (int j = 0; j < TN; j++) { acc1[i][j] = 0.0f; acc2[i][j] = 0.0f; }

    for (int k0 = 0; k0 < K; k0 += BK) {
        #pragma unroll
        for (int it = 0; it < 2; it++) {
            int l = t + 256 * it;
            int row = l >> 2;
            int kc = (l & 3) * 4;
            float4 v = make_float4(0.f, 0.f, 0.f, 0.f);
            int gr = m0 + row;
            if (gr < M) v = *(const float4*)&A[(size_t)gr * K + k0 + kc];
            As[kc + 0][row] = v.x;
            As[kc + 1][row] = v.y;
            As[kc + 2][row] = v.z;
            As[kc + 3][row] = v.w;
        }
        {
            int row = t >> 4;
            int nc = (t & 15) * 4;
            *(float4*)&Bs1[row][nc] = *(const float4*)&B1[(size_t)(k0 + row) * N + n0 + nc];
            *(float4*)&Bs2[row][nc] = *(const float4*)&B2[(size_t)(k0 + row) * N + n0 + nc];
        }
        __syncthreads();
        #pragma unroll
        for (int k = 0; k < BK; k++) {
            float4 a0 = *(float4*)&As[k][ty * TM];
            float4 a1 = *(float4*)&As[k][ty * TM + 4];
            float ar[TM] = {a0.x, a0.y, a0.z, a0.w, a1.x, a1.y, a1.z, a1.w};
            float4 b1 = *(float4*)&Bs1[k][tx * TN];
            float4 b2 = *(float4*)&Bs2[k][tx * TN];
            float br1[TN] = {b1.x, b1.y, b1.z, b1.w};
            float br2[TN] = {b2.x, b2.y, b2.z, b2.w};
            #pragma unroll
            for (int i = 0; i < TM; i++)
                #pragma unroll
                for (int j = 0; j < TN; j++) {
                    acc1[i][j] += ar[i] * br1[j];
                    acc2[i][j] += ar[i] * br2[j];
                }
        }
        __syncthreads();
    }

    #pragma unroll
    for (int i = 0; i < TM; i++) {
        int gr = m0 + ty * TM + i;
        if (gr >= M) continue;
        float4 o1, o2;
        o1.x = acc1[i][0]; o1.y = acc1[i][1]; o1.z = acc1[i][2]; o1.w = acc1[i][3];
        o2.x = acc2[i][0]; o2.y = acc2[i][1]; o2.z = acc2[i][2]; o2.w = acc2[i][3];
        *(float4*)&C1[(size_t)gr * N + n0 + tx * TN] = o1;
        *(float4*)&C2[(size_t)gr * N + n0 + tx * TN] = o2;
    }
}

// ---------------- fused edge kernel (v2) ----------------
// 128 threads. Thread t owns filter columns {t, 128+t, 256+t} (Wf 60 regs).
// EB=16 edges per batch; phase1: filter+gather -> fo_sh; phase2: messages + v4 red.
#define EB 16
__global__ void __launch_bounds__(128, 5) edge_kernel(
    const float* __restrict__ es_g, const float* __restrict__ ev_g,
    const float* __restrict__ norms, const int* __restrict__ eidx,
    const float* __restrict__ Wf, const float* __restrict__ bf,
    const float* __restrict__ nsv, int E)
{
    __shared__ float es_sh[EB][ESZ];
    __shared__ __align__(16) float fo_sh[EB][3 * D];
    __shared__ int   src_sh[EB], dst_sh[EB];
    __shared__ float ev_sh[EB][3];
    __shared__ float fc_sh[EB];

    int t = threadIdx.x;

    // Wf strided columns in registers: 3 x 20
    float wf0[ESZ], wf1[ESZ], wf2[ESZ];
    #pragma unroll
    for (int k = 0; k < ESZ; k++) {
        wf0[k] = __ldg(&Wf[k * 384 + t]);
        wf1[k] = __ldg(&Wf[k * 384 + D + t]);
        wf2[k] = __ldg(&Wf[k * 384 + 2 * D + t]);
    }
    float bf0 = __ldg(&bf[t]);
    float bf1 = __ldg(&bf[D + t]);
    float bf2 = __ldg(&bf[2 * D + t]);

    int nbatch = (E + EB - 1) / EB;
    for (int b = blockIdx.x; b < nbatch; b += gridDim.x) {
        int e0 = b * EB;
        int ecount = min(EB, E - e0);

        // ---- phase 0: stage edge data ----
        #pragma unroll
        for (int it = 0; it < (EB * ESZ + 127) / 128; it++) {
            int l = t + 128 * it;
            if (l < EB * ESZ) {
                int e = l / ESZ;
                es_sh[e][l % ESZ] = (e < ecount) ? __ldg(&es_g[(size_t)e0 * ESZ + l]) : 0.0f;
            }
        }
        if (t < EB) {
            if (t < ecount) {
                int ge = e0 + t;
                src_sh[t] = eidx[2 * ge];
                dst_sh[t] = eidx[2 * ge + 1];
                ev_sh[t][0] = ev_g[3 * ge];
                ev_sh[t][1] = ev_g[3 * ge + 1];
                ev_sh[t][2] = ev_g[3 * ge + 2];
                float nrm = norms[ge];
                fc_sh[t] = (nrm < CUTOFF) ? 0.5f * (cospif(nrm / CUTOFF) + 1.0f) : 0.0f;
            } else {
                src_sh[t] = 0; dst_sh[t] = 0;
                ev_sh[t][0] = ev_sh[t][1] = ev_sh[t][2] = 0.f;
                fc_sh[t] = 0.f;
            }
        }
        __syncthreads();

        // ---- phase 1: filter_output ----
        #pragma unroll 4
        for (int e = 0; e < EB; e++) {
            if (e >= ecount) break;
            int src = src_sh[e];
            const float* sop = g_so + (size_t)src * 384;
            float so0 = __ldg(sop + t);
            float so1 = __ldg(sop + D + t);
            float so2 = __ldg(sop + 2 * D + t);
            float a0 = bf0, a1 = bf1, a2 = bf2;
            #pragma unroll
            for (int k = 0; k < ESZ; k++) {
                float ek = es_sh[e][k];
                a0 = fmaf(ek, wf0[k], a0);
                a1 = fmaf(ek, wf1[k], a1);
                a2 = fmaf(ek, wf2[k], a2);
            }
            float fc = fc_sh[e];
            fo_sh[e][t]         = a0 * fc * so0;
            fo_sh[e][D + t]     = a1 * fc * so1;
            fo_sh[e][2 * D + t] = a2 * fc * so2;
        }
        __syncthreads();

        // ---- phase 2: messages + scatter ----
        {
            int s = t & 31;
            int grp = t >> 5;
            #pragma unroll
            for (int ee = 0; ee < EB / 4; ee++) {
                int e = grp + 4 * ee;
                if (e >= ecount) continue;
                int dst = dst_sh[e];
                int src = src_sh[e];
                float4 gn = *(float4*)&fo_sh[e][4 * s];
                float4 ge = *(float4*)&fo_sh[e][D + 4 * s];
                float4 ms = *(float4*)&fo_sh[e][2 * D + 4 * s];
                red_add_v4(&g_s[(size_t)dst * D + 4 * s], ms);
                #pragma unroll
                for (int c = 0; c < 3; c++) {
                    float evc = ev_sh[e][c];
                    float4 nv = __ldg((const float4*)&nsv[((size_t)src * 3 + c) * D + 4 * s]);
                    float4 mv;
                    mv.x = nv.x * gn.x + ge.x * evc;
                    mv.y = nv.y * gn.y + ge.y * evc;
                    mv.z = nv.z * gn.z + ge.z * evc;
                    mv.w = nv.w * gn.w + ge.w * evc;
                    red_add_v4(&g_v[((size_t)dst * 3 + c) * D + 4 * s], mv);
                }
            }
        }
        __syncthreads();
    }
}

// ---------------- per-node: Vv_sq, ip, concat ----------------
__global__ void vsq_ip_cat_kernel(int n) {
    int node = blockIdx.x;
    int i = threadIdx.x;  // 128
    float vsq = 0.f, ipv = 0.f;
    #pragma unroll
    for (int c = 0; c < 3; c++) {
        float u = g_Uv[((size_t)node * 3 + c) * D + i];
        float w = g_Vv[((size_t)node * 3 + c) * D + i];
        vsq += w * w;
        ipv += u * w;
    }
    g_cat[(size_t)node * 256 + i]       = g_s[(size_t)node * D + i];
    g_cat[(size_t)node * 256 + D + i]   = vsq;
    g_ip[(size_t)node * D + i]          = ipv;
}

// ---------------- final elementwise ----------------
__global__ void final_kernel(float* __restrict__ out, int n) {
    int node = blockIdx.x;
    int i = threadIdx.x;  // 128
    const float* a = &g_a[(size_t)node * 384];
    float a_ss = a[i];
    float a_sv = a[D + i];
    float a_vv = a[2 * D + i];
    out[(size_t)node * D + i] =
        g_s[(size_t)node * D + i] + a_ss + a_sv * g_ip[(size_t)node * D + i];
    float* vout = out + (size_t)n * D;
    #pragma unroll
    for (int c = 0; c < 3; c++) {
        size_t idx = ((size_t)node * 3 + c) * D + i;
        vout[idx] = g_v[idx] + a_vv * g_Uv[idx];
    }
}

// ---------------- launch ----------------
extern "C" void kernel_launch(void* const* d_in, const int* in_sizes, int n_in,
                              void* d_out, int out_size) {
    const float* ns  = (const float*)d_in[0];
    const float* nv  = (const float*)d_in[1];
    const float* es  = (const float*)d_in[2];
    const float* ev  = (const float*)d_in[3];
    const float* en  = (const float*)d_in[4];
    const int*   ei  = (const int*)  d_in[5];
    const float* Wf  = (const float*)d_in[6];
    const float* bf  = (const float*)d_in[7];
    const float* Wm1 = (const float*)d_in[8];
    const float* bm1 = (const float*)d_in[9];
    const float* Wm2 = (const float*)d_in[10];
    const float* bm2 = (const float*)d_in[11];
    const float* WU  = (const float*)d_in[12];
    const float* WV  = (const float*)d_in[13];
    const float* Wa1 = (const float*)d_in[14];
    const float* ba1 = (const float*)d_in[15];
    const float* Wa2 = (const float*)d_in[16];
    const float* ba2 = (const float*)d_in[17];

    int n = in_sizes[0] / D;          // nodes
    int E = in_sizes[4];              // edges (edge_norms count)
    float* out = (float*)d_out;

    float *p_h1, *p_so, *p_v, *p_Uv, *p_Vv, *p_cat, *p_h2, *p_a;
    cudaGetSymbolAddress((void**)&p_h1,  g_h1);
    cudaGetSymbolAddress((void**)&p_so,  g_so);
    cudaGetSymbolAddress((void**)&p_v,   g_v);
    cudaGetSymbolAddress((void**)&p_Uv,  g_Uv);
    cudaGetSymbolAddress((void**)&p_Vv,  g_Vv);
    cudaGetSymbolAddress((void**)&p_cat, g_cat);
    cudaGetSymbolAddress((void**)&p_h2,  g_h2);
    cudaGetSymbolAddress((void**)&p_a,   g_a);

    // 1. init accumulators s = ns, v = nv
    init_copy_kernel<<<2048, 256>>>(ns, nv, n);

    // 2. H1 = silu(ns @ Wm1 + bm1)   [n,128]
    {
        dim3 grid((n + 127) / 128, 128 / 64);
        sgemm_kernel<true, true><<<grid, 256>>>(ns, Wm1, bm1, p_h1, n, 128, 128);
    }
    // 3. SO = H1 @ Wm2 + bm2         [n,384]
    {
        dim3 grid((n + 127) / 128, 384 / 64);
        sgemm_kernel<false, true><<<grid, 256>>>(p_h1, Wm2, bm2, p_so, n, 384, 128);
    }
    // 4. fused edge kernel
    {
        int nbatch = (E + EB - 1) / EB;
        int grid = nbatch < 2960 ? nbatch : 2960;
        edge_kernel<<<grid, 128>>>(es, ev, en, ei, Wf, bf, nv, E);
    }
    // 5/6. Uv = v @ WU, Vv = v @ WV  (rows = 3n) in one pass over A
    {
        dim3 grid((3 * n + 127) / 128, 128 / 64);
        sgemm_dual_kernel<<<grid, 256>>>(p_v, WU, WV, p_Uv, p_Vv, 3 * n, 128, 128);
    }
    // 7. Vv_sq, ip, cat
    vsq_ip_cat_kernel<<<n, 128>>>(n);

    // 8. H2 = silu(cat @ Wa1 + ba1)  [n,128], K=256
    {
        dim3 grid((n + 127) / 128, 128 / 64);
        sgemm_kernel<true, true><<<grid, 256>>>(p_cat, Wa1, ba1, p_h2, n, 128, 256);
    }
    // 9. A = H2 @ Wa2 + ba2          [n,384]
    {
        dim3 grid((n + 127) / 128, 384 / 64);
        sgemm_kernel<false, true><<<grid, 256>>>(p_h2, Wa2, ba2, p_a, n, 384, 128);
    }
    // 10. final
    final_kernel<<<n, 128>>>(out, n);
}